// round 1
// baseline (speedup 1.0000x reference)
#include <cuda_runtime.h>
#include <math.h>

#define BB 128
#define TT 256
#define LL 512
#define HH 512
#define CC 95
#define ML 26

// ---------------- device scratch (static: no runtime allocation) ----------------
__device__ float g_xEmb[BB * TT * HH];   // 64 MB: x @ Wi + bi
__device__ float g_sEmb[BB * HH];
__device__ float g_ctx[BB * LL];
__device__ float g_gates[BB * 3072];     // [b][0:1536]=gi, [1536:3072]=gh
__device__ float g_h[BB * HH];

// ---------------- FMA-only fast math (avoid MUFU pipe entirely) ----------------
__device__ __forceinline__ float fast_rcp_pos(float q) {
    // bit-trick initial guess + 3 Newton iterations (error < 1e-7 rel)
    float r = __uint_as_float(0x7EF127EAu - __float_as_uint(q));
    r = r * (2.0f - q * r);
    r = r * (2.0f - q * r);
    r = r * (2.0f - q * r);
    return r;
}

__device__ __forceinline__ float fast_tanh(float x) {
    // Eigen-style rational minimax, valid (clamped) on [-7.9053, 7.9053]
    float cx = fminf(fmaxf(x, -7.90531110763549805f), 7.90531110763549805f);
    float x2 = cx * cx;
    float p = fmaf(x2, -2.76076847742355e-16f, 2.00018790482477e-13f);
    p = fmaf(p, x2, -8.60467152213735e-11f);
    p = fmaf(p, x2, 5.12229709037114e-08f);
    p = fmaf(p, x2, 1.48572235717979e-05f);
    p = fmaf(p, x2, 6.37261928875436e-04f);
    p = fmaf(p, x2, 4.89352455891786e-03f);
    p = cx * p;
    float q = fmaf(x2, 1.19825839466702e-06f, 1.18534705686654e-04f);
    q = fmaf(q, x2, 2.26843463243900e-03f);
    q = fmaf(q, x2, 4.89352518554385e-03f);
    return p * fast_rcp_pos(q);
}

// ---------------- generic full-tile fp32 NN GEMM: C = A@B + bias ----------------
template <int BM, int BN, int BK, int TM, int TN>
__global__ void sgemm_nn_kernel(const float* __restrict__ A,
                                const float* __restrict__ B,
                                const float* __restrict__ bias,
                                float* __restrict__ C,
                                int M, int N, int K) {
    constexpr int THREADS = (BM / TM) * (BN / TN);
    __shared__ float As[BK][BM + 1];
    __shared__ float Bs[BK][BN];
    const int tid = threadIdx.x;
    const int tx = tid % (BN / TN);
    const int ty = tid / (BN / TN);
    const int m0 = blockIdx.y * BM;
    const int n0 = blockIdx.x * BN;
    float acc[TM][TN] = {};
    for (int k0 = 0; k0 < K; k0 += BK) {
#pragma unroll
        for (int i = 0; i < BM * BK / THREADS; ++i) {
            int idx = tid + i * THREADS;
            int m = idx / BK, k = idx % BK;
            As[k][m] = A[(size_t)(m0 + m) * K + k0 + k];
        }
#pragma unroll
        for (int i = 0; i < BK * BN / THREADS; ++i) {
            int idx = tid + i * THREADS;
            int n = idx % BN, k = idx / BN;
            Bs[k][n] = B[(size_t)(k0 + k) * N + n0 + n];
        }
        __syncthreads();
#pragma unroll
        for (int kk = 0; kk < BK; ++kk) {
            float af[TM], bf[TN];
#pragma unroll
            for (int i = 0; i < TM; ++i) af[i] = As[kk][ty * TM + i];
#pragma unroll
            for (int j = 0; j < TN; ++j) bf[j] = Bs[kk][tx * TN + j];
#pragma unroll
            for (int i = 0; i < TM; ++i)
#pragma unroll
                for (int j = 0; j < TN; ++j)
                    acc[i][j] = fmaf(af[i], bf[j], acc[i][j]);
        }
        __syncthreads();
    }
#pragma unroll
    for (int i = 0; i < TM; ++i) {
        int m = m0 + ty * TM + i;
#pragma unroll
        for (int j = 0; j < TN; ++j) {
            int n = n0 + tx * TN + j;
            C[(size_t)m * N + n] = acc[i][j] + bias[n];
        }
    }
}

// ------------- NT GEMM for GRU gates: C[m, col0+j] = sum_k A(m,k) * W[j,k] + bias[j]
// GATHER=true: A(m,k) = k<512 ? emb[y_m][k] : ctx[m][k-512]   (teacher-forced input)
template <int BM, int BN, int BK, int TM, int TN, bool GATHER>
__global__ void gemm_nt_kernel(const float* __restrict__ A,
                               const float* __restrict__ emb,
                               const int* __restrict__ targets,
                               const float* __restrict__ W,
                               const float* __restrict__ bias,
                               float* __restrict__ C,
                               int K, int col0, int step) {
    constexpr int THREADS = (BM / TM) * (BN / TN);
    __shared__ float As[BK][BM + 1];
    __shared__ float Wsm[BK][BN + 1];
    __shared__ int sy[BM];
    const int tid = threadIdx.x;
    const int tx = tid % (BN / TN);
    const int ty = tid / (BN / TN);
    const int m0 = blockIdx.y * BM;
    const int n0 = blockIdx.x * BN;
    if (GATHER) {
        if (tid < BM) {
            int m = m0 + tid;
            sy[tid] = (step == 0) ? CC : targets[m * ML + step - 1];
        }
        __syncthreads();
    }
    float acc[TM][TN] = {};
    for (int k0 = 0; k0 < K; k0 += BK) {
#pragma unroll
        for (int i = 0; i < BM * BK / THREADS; ++i) {
            int idx = tid + i * THREADS;
            int m = idx / BK, k = idx % BK;
            int gk = k0 + k;
            float v;
            if (GATHER) {
                v = (gk < HH) ? emb[sy[m] * HH + gk]
                              : g_ctx[(m0 + m) * LL + gk - HH];
            } else {
                v = A[(m0 + m) * K + gk];
            }
            As[k][m] = v;
        }
#pragma unroll
        for (int i = 0; i < BN * BK / THREADS; ++i) {
            int idx = tid + i * THREADS;
            int j = idx / BK, k = idx % BK;
            Wsm[k][j] = W[(n0 + j) * K + k0 + k];
        }
        __syncthreads();
#pragma unroll
        for (int kk = 0; kk < BK; ++kk) {
            float af[TM], wf[TN];
#pragma unroll
            for (int i = 0; i < TM; ++i) af[i] = As[kk][ty * TM + i];
#pragma unroll
            for (int j = 0; j < TN; ++j) wf[j] = Wsm[kk][tx * TN + j];
#pragma unroll
            for (int i = 0; i < TM; ++i)
#pragma unroll
                for (int j = 0; j < TN; ++j)
                    acc[i][j] = fmaf(af[i], wf[j], acc[i][j]);
        }
        __syncthreads();
    }
#pragma unroll
    for (int i = 0; i < TM; ++i) {
        int m = m0 + ty * TM + i;
#pragma unroll
        for (int j = 0; j < TN; ++j) {
            int jj = n0 + tx * TN + j;
            C[m * 3072 + col0 + jj] = acc[i][j] + bias[jj];
        }
    }
}

// ---------------- fused attention: e -> softmax -> ctx (one block per batch) ----
__global__ void attention_kernel(const float* __restrict__ x,
                                 const float* __restrict__ wo,
                                 const float* __restrict__ bo) {
    const int b = blockIdx.x;
    const int tid = threadIdx.x;   // 256
    const int lane = tid & 31;
    const int warp = tid >> 5;
    __shared__ float aw_s[TT];
    __shared__ float red_s[16];

    float wo_r[16], se_r[16];
#pragma unroll
    for (int i = 0; i < 16; ++i) {
        wo_r[i] = wo[lane + 32 * i];
        se_r[i] = g_sEmb[b * HH + lane + 32 * i];
    }
    const float bo_v = *bo;
    const float* xe = g_xEmb + (size_t)b * TT * HH;

    for (int t = warp; t < TT; t += 8) {
        const float* row = xe + t * HH;
        float acc = 0.f;
#pragma unroll
        for (int i = 0; i < 16; ++i) {
            float v = row[lane + 32 * i] + se_r[i];
            acc = fmaf(wo_r[i], fast_tanh(v), acc);
        }
#pragma unroll
        for (int off = 16; off > 0; off >>= 1)
            acc += __shfl_xor_sync(0xffffffffu, acc, off);
        if (lane == 0) aw_s[t] = acc + bo_v;
    }
    __syncthreads();

    // softmax over T=256 (one value per thread)
    float e = aw_s[tid];
    float m = e;
#pragma unroll
    for (int off = 16; off > 0; off >>= 1)
        m = fmaxf(m, __shfl_xor_sync(0xffffffffu, m, off));
    if (lane == 0) red_s[warp] = m;
    __syncthreads();
    if (tid == 0) {
        float mm = red_s[0];
#pragma unroll
        for (int w = 1; w < 8; ++w) mm = fmaxf(mm, red_s[w]);
        red_s[8] = mm;
    }
    __syncthreads();
    const float mx = red_s[8];
    float ex = expf(e - mx);
    float s = ex;
#pragma unroll
    for (int off = 16; off > 0; off >>= 1)
        s += __shfl_xor_sync(0xffffffffu, s, off);
    if (lane == 0) red_s[warp] = s;
    __syncthreads();
    if (tid == 0) {
        float ss = 0.f;
#pragma unroll
        for (int w = 0; w < 8; ++w) ss += red_s[w];
        red_s[9] = 1.0f / ss;
    }
    __syncthreads();
    aw_s[tid] = ex * red_s[9];
    __syncthreads();

    // ctx[b][l] = sum_t aw[t] * x[b][t][l]  (coalesced over l)
    const float* xb = x + (size_t)b * TT * LL;
    float a0 = 0.f, a1 = 0.f;
#pragma unroll 4
    for (int t = 0; t < TT; ++t) {
        float a = aw_s[t];
        a0 = fmaf(a, xb[t * LL + tid], a0);
        a1 = fmaf(a, xb[t * LL + tid + 256], a1);
    }
    g_ctx[b * LL + tid] = a0;
    g_ctx[b * LL + tid + 256] = a1;
}

// ------ fused GRU pointwise + output projection + log-softmax (block per batch) --
__global__ void gru_out_kernel(const float* __restrict__ Wout,
                               const float* __restrict__ bout,
                               float* __restrict__ out, int step) {
    const int b = blockIdx.x;
    const int tid = threadIdx.x;   // 512
    __shared__ float hs[HH];
    __shared__ float lg[CC];
    __shared__ float red2[2];
    const float* g = g_gates + b * 3072;
    float gir = g[tid], giz = g[tid + 512], gin = g[tid + 1024];
    float ghr = g[tid + 1536], ghz = g[tid + 2048], ghn = g[tid + 2560];
    float r = 1.f / (1.f + expf(-(gir + ghr)));
    float z = 1.f / (1.f + expf(-(giz + ghz)));
    float n = tanhf(gin + r * ghn);
    float hv = (1.f - z) * n + z * g_h[b * HH + tid];
    g_h[b * HH + tid] = hv;
    hs[tid] = hv;
    __syncthreads();
    if (tid < CC) {
        float acc = bout[tid];
#pragma unroll 8
        for (int k = 0; k < HH; ++k)
            acc = fmaf(hs[k], Wout[k * CC + tid], acc);
        lg[tid] = acc;
    }
    __syncthreads();
    if (tid == 0) {
        float mx = lg[0];
        for (int c = 1; c < CC; ++c) mx = fmaxf(mx, lg[c]);
        float ssum = 0.f;
        for (int c = 0; c < CC; ++c) ssum += expf(lg[c] - mx);
        red2[0] = mx;
        red2[1] = logf(ssum);
    }
    __syncthreads();
    if (tid < CC)
        out[(size_t)step * BB * CC + b * CC + tid] = lg[tid] - red2[0] - red2[1];
}

__global__ void zero_kernel(float* p) {
    p[blockIdx.x * blockDim.x + threadIdx.x] = 0.f;
}

// --------------------------------- launcher -------------------------------------
extern "C" void kernel_launch(void* const* d_in, const int* in_sizes, int n_in,
                              void* d_out, int out_size) {
    (void)in_sizes; (void)n_in; (void)out_size;
    const float* x       = (const float*)d_in[0];
    const int*   targets = (const int*)  d_in[1];
    const float* emb     = (const float*)d_in[2];
    const float* Wi      = (const float*)d_in[3];
    const float* bi      = (const float*)d_in[4];
    const float* Ws      = (const float*)d_in[5];
    const float* bs      = (const float*)d_in[6];
    const float* wo      = (const float*)d_in[7];
    const float* bo      = (const float*)d_in[8];
    const float* W_ih    = (const float*)d_in[9];
    const float* W_hh    = (const float*)d_in[10];
    const float* b_ih    = (const float*)d_in[11];
    const float* b_hh    = (const float*)d_in[12];
    const float* Wout    = (const float*)d_in[13];
    const float* bout    = (const float*)d_in[14];
    float* out = (float*)d_out;

    float *p_xEmb, *p_h, *p_sEmb, *p_gates;
    cudaGetSymbolAddress((void**)&p_xEmb, g_xEmb);
    cudaGetSymbolAddress((void**)&p_h, g_h);
    cudaGetSymbolAddress((void**)&p_sEmb, g_sEmb);
    cudaGetSymbolAddress((void**)&p_gates, g_gates);

    // h0 = 0
    zero_kernel<<<128, 512>>>(p_h);

    // xEmb = x2d @ Wi + bi   [32768, 512] = [32768,512] @ [512,512]
    sgemm_nn_kernel<128, 128, 8, 8, 8>
        <<<dim3(HH / 128, (BB * TT) / 128), 256>>>(x, Wi, bi, p_xEmb,
                                                   BB * TT, HH, LL);

    for (int step = 0; step < ML; ++step) {
        // sEmb = h @ Ws + bs   [128,512]
        sgemm_nn_kernel<32, 64, 8, 4, 4>
            <<<dim3(HH / 64, BB / 32), 128>>>(p_h, Ws, bs, p_sEmb, BB, HH, HH);

        // e/softmax/ctx fused
        attention_kernel<<<BB, 256>>>(x, wo, bo);

        // gi = [emb(y), ctx] @ W_ih^T + b_ih   (K = 1024, gathered A)
        gemm_nt_kernel<64, 32, 16, 4, 2, true>
            <<<dim3(1536 / 32, BB / 64), 256>>>(nullptr, emb, targets, W_ih,
                                                b_ih, p_gates, HH + LL, 0, step);
        // gh = h @ W_hh^T + b_hh   (K = 512)
        gemm_nt_kernel<64, 64, 16, 4, 4, false>
            <<<dim3(1536 / 64, BB / 64), 256>>>(p_h, emb, targets, W_hh,
                                                b_hh, p_gates, HH, 1536, step);

        // GRU pointwise + logits + log-softmax
        gru_out_kernel<<<BB, 512>>>(Wout, bout, out, step);
    }
}

// round 3
// speedup vs baseline: 1.9804x; 1.9804x over previous
#include <cuda_runtime.h>
#include <cuda_bf16.h>
#include <math.h>

#define BB 128
#define TT 256
#define LL 512
#define HH 512
#define CC 95
#define ML 26

// ---------------- device scratch (static: no runtime allocation) ----------------
__device__ __nv_bfloat16 g_xEmb16[BB * TT * HH];  // 32 MB
__device__ __nv_bfloat16 g_x16[BB * TT * LL];     // 32 MB
__device__ float g_e[BB * TT];
__device__ float g_sEmb[BB * HH];
__device__ float g_inp[BB * 1024];                // [emb(y), ctx]
__device__ float g_gates[BB * 3072];              // gi | gh
__device__ float g_h[BB * HH];

// ---------------- FMA-only fast math (avoid MUFU pipe) --------------------------
__device__ __forceinline__ float fast_rcp_pos(float q) {
    float r = __uint_as_float(0x7EF127EAu - __float_as_uint(q));
    r = r * (2.0f - q * r);
    r = r * (2.0f - q * r);
    r = r * (2.0f - q * r);
    return r;
}

__device__ __forceinline__ float fast_tanh(float x) {
    float cx = fminf(fmaxf(x, -7.90531110763549805f), 7.90531110763549805f);
    float x2 = cx * cx;
    float p = fmaf(x2, -2.76076847742355e-16f, 2.00018790482477e-13f);
    p = fmaf(p, x2, -8.60467152213735e-11f);
    p = fmaf(p, x2, 5.12229709037114e-08f);
    p = fmaf(p, x2, 1.48572235717979e-05f);
    p = fmaf(p, x2, 6.37261928875436e-04f);
    p = fmaf(p, x2, 4.89352455891786e-03f);
    p = cx * p;
    float q = fmaf(x2, 1.19825839466702e-06f, 1.18534705686654e-04f);
    q = fmaf(q, x2, 2.26843463243900e-03f);
    q = fmaf(q, x2, 4.89352518554385e-03f);
    return p * fast_rcp_pos(q);
}

// ---------------- one-time: bf16 copy of x --------------------------------------
__global__ void convert_x_kernel(const float* __restrict__ x) {
    int i = (blockIdx.x * 256 + threadIdx.x) * 4;
    float4 v = *(const float4*)(x + i);
    __nv_bfloat162* o = (__nv_bfloat162*)(g_x16 + i);
    o[0] = __floats2bfloat162_rn(v.x, v.y);
    o[1] = __floats2bfloat162_rn(v.z, v.w);
}

// ---------------- xEmb = x @ Wi + bi, stored bf16 -------------------------------
template <int BM, int BN, int BK, int TM, int TN>
__global__ void sgemm_bf16out_kernel(const float* __restrict__ A,
                                     const float* __restrict__ B,
                                     const float* __restrict__ bias,
                                     __nv_bfloat16* __restrict__ C,
                                     int M, int N, int K) {
    constexpr int THREADS = (BM / TM) * (BN / TN);
    __shared__ float As[BK][BM + 1];
    __shared__ float Bs[BK][BN];
    const int tid = threadIdx.x;
    const int tx = tid % (BN / TN);
    const int ty = tid / (BN / TN);
    const int m0 = blockIdx.y * BM;
    const int n0 = blockIdx.x * BN;
    float acc[TM][TN] = {};
    for (int k0 = 0; k0 < K; k0 += BK) {
#pragma unroll
        for (int i = 0; i < BM * BK / THREADS; ++i) {
            int idx = tid + i * THREADS;
            int m = idx / BK, k = idx % BK;
            As[k][m] = A[(size_t)(m0 + m) * K + k0 + k];
        }
#pragma unroll
        for (int i = 0; i < BK * BN / THREADS; ++i) {
            int idx = tid + i * THREADS;
            int n = idx % BN, k = idx / BN;
            Bs[k][n] = B[(size_t)(k0 + k) * N + n0 + n];
        }
        __syncthreads();
#pragma unroll
        for (int kk = 0; kk < BK; ++kk) {
            float af[TM], bf[TN];
#pragma unroll
            for (int i = 0; i < TM; ++i) af[i] = As[kk][ty * TM + i];
#pragma unroll
            for (int j = 0; j < TN; ++j) bf[j] = Bs[kk][tx * TN + j];
#pragma unroll
            for (int i = 0; i < TM; ++i)
#pragma unroll
                for (int j = 0; j < TN; ++j)
                    acc[i][j] = fmaf(af[i], bf[j], acc[i][j]);
        }
        __syncthreads();
    }
#pragma unroll
    for (int i = 0; i < TM; ++i) {
        int m = m0 + ty * TM + i;
#pragma unroll
        for (int j = 0; j < TN; ++j) {
            int n = n0 + tx * TN + j;
            C[(size_t)m * N + n] = __float2bfloat16(acc[i][j] + bias[n]);
        }
    }
}

// ---------------- fp32 NN GEMM (sEmb = h@Ws + bs) -------------------------------
template <int BM, int BN, int BK, int TM, int TN>
__global__ void sgemm_nn_kernel(const float* __restrict__ A,
                                const float* __restrict__ B,
                                const float* __restrict__ bias,
                                float* __restrict__ C,
                                int M, int N, int K) {
    constexpr int THREADS = (BM / TM) * (BN / TN);
    __shared__ float As[BK][BM + 1];
    __shared__ float Bs[BK][BN];
    const int tid = threadIdx.x;
    const int tx = tid % (BN / TN);
    const int ty = tid / (BN / TN);
    const int m0 = blockIdx.y * BM;
    const int n0 = blockIdx.x * BN;
    float acc[TM][TN] = {};
    for (int k0 = 0; k0 < K; k0 += BK) {
#pragma unroll
        for (int i = 0; i < BM * BK / THREADS; ++i) {
            int idx = tid + i * THREADS;
            int m = idx / BK, k = idx % BK;
            As[k][m] = A[(size_t)(m0 + m) * K + k0 + k];
        }
#pragma unroll
        for (int i = 0; i < BK * BN / THREADS; ++i) {
            int idx = tid + i * THREADS;
            int n = idx % BN, k = idx / BN;
            Bs[k][n] = B[(size_t)(k0 + k) * N + n0 + n];
        }
        __syncthreads();
#pragma unroll
        for (int kk = 0; kk < BK; ++kk) {
            float af[TM], bf[TN];
#pragma unroll
            for (int i = 0; i < TM; ++i) af[i] = As[kk][ty * TM + i];
#pragma unroll
            for (int j = 0; j < TN; ++j) bf[j] = Bs[kk][tx * TN + j];
#pragma unroll
            for (int i = 0; i < TM; ++i)
#pragma unroll
                for (int j = 0; j < TN; ++j)
                    acc[i][j] = fmaf(af[i], bf[j], acc[i][j]);
        }
        __syncthreads();
    }
#pragma unroll
    for (int i = 0; i < TM; ++i) {
        int m = m0 + ty * TM + i;
#pragma unroll
        for (int j = 0; j < TN; ++j) {
            int n = n0 + tx * TN + j;
            C[(size_t)m * N + n] = acc[i][j] + bias[n];
        }
    }
}

// ---------------- attention scores: e[b,t] = wo.tanh(xEmb+sEmb) + bo ------------
// grid (8, 128), 256 threads; each warp does 4 t-rows
__global__ void escore_kernel(const float* __restrict__ wo,
                              const float* __restrict__ bo) {
    const int b = blockIdx.y;
    const int chunk = blockIdx.x;
    const int lane = threadIdx.x & 31;
    const int warp = threadIdx.x >> 5;
    float2 wo2[8], se2[8];
    const float2* wof = (const float2*)wo;
    const float2* sef = (const float2*)(g_sEmb + b * HH);
#pragma unroll
    for (int j = 0; j < 8; ++j) {
        wo2[j] = wof[lane + 32 * j];
        se2[j] = sef[lane + 32 * j];
    }
    const float bov = *bo;
    const __nv_bfloat162* xe =
        (const __nv_bfloat162*)g_xEmb16 + (size_t)b * TT * 256;
#pragma unroll
    for (int r = 0; r < 4; ++r) {
        int t = chunk * 32 + warp * 4 + r;
        const __nv_bfloat162* row = xe + t * 256;
        float acc = 0.f;
#pragma unroll
        for (int j = 0; j < 8; ++j) {
            float2 v = __bfloat1622float2(row[lane + 32 * j]);
            acc = fmaf(wo2[j].x, fast_tanh(v.x + se2[j].x), acc);
            acc = fmaf(wo2[j].y, fast_tanh(v.y + se2[j].y), acc);
        }
#pragma unroll
        for (int off = 16; off > 0; off >>= 1)
            acc += __shfl_xor_sync(0xffffffffu, acc, off);
        if (lane == 0) g_e[b * TT + t] = acc + bov;
    }
}

// -------- softmax + ctx + emb gather -> g_inp.  grid (2, 128), 128 threads ------
__global__ void ctx_kernel(const float* __restrict__ emb,
                           const int* __restrict__ targets, int step) {
    const int b = blockIdx.y;
    const int half = blockIdx.x;
    const int tid = threadIdx.x;
    const int lane = tid & 31, warp = tid >> 5;
    __shared__ float aw[TT];
    __shared__ float red[8];

    float e0 = g_e[b * TT + tid];
    float e1 = g_e[b * TT + 128 + tid];
    float m = fmaxf(e0, e1);
#pragma unroll
    for (int off = 16; off > 0; off >>= 1)
        m = fmaxf(m, __shfl_xor_sync(0xffffffffu, m, off));
    if (lane == 0) red[warp] = m;
    __syncthreads();
    if (tid == 0)
        red[4] = fmaxf(fmaxf(red[0], red[1]), fmaxf(red[2], red[3]));
    __syncthreads();
    const float mx = red[4];
    float x0 = __expf(e0 - mx), x1 = __expf(e1 - mx);
    float s = x0 + x1;
#pragma unroll
    for (int off = 16; off > 0; off >>= 1)
        s += __shfl_xor_sync(0xffffffffu, s, off);
    if (lane == 0) red[warp] = s;
    __syncthreads();
    if (tid == 0) red[5] = 1.0f / (red[0] + red[1] + red[2] + red[3]);
    __syncthreads();
    const float inv = red[5];
    aw[tid] = x0 * inv;
    aw[tid + 128] = x1 * inv;

    // emb gather (this block covers 256 dims of the emb part)
    const int y = (step == 0) ? CC : targets[b * ML + step - 1];
    g_inp[b * 1024 + half * 256 + tid] = emb[y * HH + half * 256 + tid];
    g_inp[b * 1024 + half * 256 + 128 + tid] = emb[y * HH + half * 256 + 128 + tid];
    __syncthreads();

    // ctx over 256 bf162 units (this block covers 128 of them)
    const int d = half * 128 + tid;
    const __nv_bfloat162* xb =
        (const __nv_bfloat162*)g_x16 + (size_t)b * TT * 256 + d;
    float ax = 0.f, ay = 0.f;
#pragma unroll 8
    for (int t = 0; t < TT; ++t) {
        float a = aw[t];
        float2 v = __bfloat1622float2(xb[t * 256]);
        ax = fmaf(a, v.x, ax);
        ay = fmaf(a, v.y, ay);
    }
    g_inp[b * 1024 + 512 + 2 * d] = ax;
    g_inp[b * 1024 + 512 + 2 * d + 1] = ay;
}

// ---------- fused GRU gate GEMM: C[128,3072] = gi | gh (NT) ---------------------
// cols [0,1536): A=g_inp (K=1024), W_ih ; cols [1536,3072): A=g_h (K=512), W_hh
__global__ void gates_kernel(const float* __restrict__ W_ih,
                             const float* __restrict__ W_hh,
                             const float* __restrict__ b_ih,
                             const float* __restrict__ b_hh) {
    constexpr int BM = 64, BN = 64, BK = 16, TM = 4, TN = 4;
    const int tid = threadIdx.x;  // 256
    const int tx = tid % 16;
    const int ty = tid / 16;
    const int n0 = blockIdx.x * BN;
    const int m0 = blockIdx.y * BM;
    const bool hh = (n0 >= 1536);
    const float* A = hh ? g_h : g_inp;
    const int K = hh ? 512 : 1024;
    const float* W = hh ? W_hh : W_ih;
    const float* bias = hh ? b_hh : b_ih;
    const int jbase = hh ? n0 - 1536 : n0;

    __shared__ float As[BK][BM + 1];
    __shared__ float Wsm[BK][BN + 1];
    float acc[TM][TN] = {};
    for (int k0 = 0; k0 < K; k0 += BK) {
#pragma unroll
        for (int i = 0; i < 4; ++i) {
            int idx = tid + i * 256;
            int m = idx / BK, k = idx % BK;
            As[k][m] = A[(m0 + m) * K + k0 + k];
        }
#pragma unroll
        for (int i = 0; i < 4; ++i) {
            int idx = tid + i * 256;
            int j = idx / BK, k = idx % BK;
            Wsm[k][j] = W[(jbase + j) * K + k0 + k];
        }
        __syncthreads();
#pragma unroll
        for (int kk = 0; kk < BK; ++kk) {
            float af[TM], wf[TN];
#pragma unroll
            for (int i = 0; i < TM; ++i) af[i] = As[kk][ty * TM + i];
#pragma unroll
            for (int j = 0; j < TN; ++j) wf[j] = Wsm[kk][tx * TN + j];
#pragma unroll
            for (int i = 0; i < TM; ++i)
#pragma unroll
                for (int j = 0; j < TN; ++j)
                    acc[i][j] = fmaf(af[i], wf[j], acc[i][j]);
        }
        __syncthreads();
    }
#pragma unroll
    for (int i = 0; i < TM; ++i) {
        int m = m0 + ty * TM + i;
#pragma unroll
        for (int j = 0; j < TN; ++j) {
            int jl = tx * TN + j;
            g_gates[m * 3072 + n0 + jl] = acc[i][j] + bias[jbase + jl];
        }
    }
}

// ------ GRU pointwise + output projection + log-softmax (block per batch) -------
__global__ void gru_out_kernel(const float* __restrict__ Wout,
                               const float* __restrict__ bout,
                               float* __restrict__ out, int step) {
    const int b = blockIdx.x;
    const int tid = threadIdx.x;  // 512
    const int lane = tid & 31, warp = tid >> 5;
    __shared__ float hs[HH];
    __shared__ float part[CC][4];
    __shared__ float lg[CC];
    __shared__ float red[8];
    __shared__ float red2[2];
    const float* g = g_gates + b * 3072;
    float gir = g[tid], giz = g[tid + 512], gin = g[tid + 1024];
    float ghr = g[tid + 1536], ghz = g[tid + 2048], ghn = g[tid + 2560];
    float r = 1.f / (1.f + __expf(-(gir + ghr)));
    float z = 1.f / (1.f + __expf(-(giz + ghz)));
    float n = fast_tanh(gin + r * ghn);
    float hv = (1.f - z) * n + z * g_h[b * HH + tid];
    g_h[b * HH + tid] = hv;
    hs[tid] = hv;
    __syncthreads();
    if (tid < 380) {
        int c = tid >> 2, ks = tid & 3;
        float acc = 0.f;
        const float* wp = Wout + (ks * 128) * CC + c;
        const float* hp = hs + ks * 128;
#pragma unroll 8
        for (int k = 0; k < 128; ++k) acc = fmaf(hp[k], wp[k * CC], acc);
        part[c][ks] = acc;
    }
    __syncthreads();
    if (tid < CC)
        lg[tid] = part[tid][0] + part[tid][1] + part[tid][2] + part[tid][3] +
                  bout[tid];
    __syncthreads();
    // log-sum-exp over 95 (first 4 warps)
    if (tid < 128) {
        float v = (tid < CC) ? lg[tid] : -1e30f;
        float m = v;
#pragma unroll
        for (int off = 16; off > 0; off >>= 1)
            m = fmaxf(m, __shfl_xor_sync(0xffffffffu, m, off));
        if (lane == 0) red[warp] = m;
    }
    __syncthreads();
    if (tid == 0)
        red2[0] = fmaxf(fmaxf(red[0], red[1]), fmaxf(red[2], red[3]));
    __syncthreads();
    if (tid < 128) {
        float v = (tid < CC) ? __expf(lg[tid] - red2[0]) : 0.f;
#pragma unroll
        for (int off = 16; off > 0; off >>= 1)
            v += __shfl_xor_sync(0xffffffffu, v, off);
        if (lane == 0) red[4 + warp] = v;
    }
    __syncthreads();
    if (tid == 0)
        red2[1] = logf(red[4] + red[5] + red[6] + red[7]);
    __syncthreads();
    if (tid < CC)
        out[(size_t)step * BB * CC + b * CC + tid] =
            lg[tid] - red2[0] - red2[1];
}

__global__ void zero_kernel(float* p) {
    p[blockIdx.x * blockDim.x + threadIdx.x] = 0.f;
}

// --------------------------------- launcher -------------------------------------
extern "C" void kernel_launch(void* const* d_in, const int* in_sizes, int n_in,
                              void* d_out, int out_size) {
    (void)in_sizes; (void)n_in; (void)out_size;
    const float* x       = (const float*)d_in[0];
    const int*   targets = (const int*)  d_in[1];
    const float* emb     = (const float*)d_in[2];
    const float* Wi      = (const float*)d_in[3];
    const float* bi      = (const float*)d_in[4];
    const float* Ws      = (const float*)d_in[5];
    const float* bs      = (const float*)d_in[6];
    const float* wo      = (const float*)d_in[7];
    const float* bo      = (const float*)d_in[8];
    const float* W_ih    = (const float*)d_in[9];
    const float* W_hh    = (const float*)d_in[10];
    const float* b_ih    = (const float*)d_in[11];
    const float* b_hh    = (const float*)d_in[12];
    const float* Wout    = (const float*)d_in[13];
    const float* bout    = (const float*)d_in[14];
    float* out = (float*)d_out;

    float *p_h, *p_sEmb;
    __nv_bfloat16* p_xEmb16;
    cudaGetSymbolAddress((void**)&p_xEmb16, g_xEmb16);
    cudaGetSymbolAddress((void**)&p_h, g_h);
    cudaGetSymbolAddress((void**)&p_sEmb, g_sEmb);

    // one-time: h=0, bf16 copy of x, xEmb = x@Wi + bi (bf16 out)
    zero_kernel<<<128, 512>>>(p_h);
    convert_x_kernel<<<(BB * TT * LL) / (256 * 4), 256>>>(x);
    sgemm_bf16out_kernel<128, 128, 16, 8, 8>
        <<<dim3(HH / 128, (BB * TT) / 128), 256>>>(x, Wi, bi, p_xEmb16,
                                                   BB * TT, HH, LL);

    for (int step = 0; step < ML; ++step) {
        // sEmb = h @ Ws + bs
        sgemm_nn_kernel<32, 32, 8, 2, 2>
            <<<dim3(HH / 32, BB / 32), 256>>>(p_h, Ws, bs, p_sEmb, BB, HH, HH);
        // e scores
        escore_kernel<<<dim3(8, BB), 256>>>(wo, bo);
        // softmax + ctx + emb gather
        ctx_kernel<<<dim3(2, BB), 128>>>(emb, targets, step);
        // gi | gh
        gates_kernel<<<dim3(3072 / 64, BB / 64), 256>>>(W_ih, W_hh, b_ih, b_hh);
        // GRU pointwise + logits + log-softmax
        gru_out_kernel<<<BB, 512>>>(Wout, bout, out, step);
    }
}

// round 4
// speedup vs baseline: 4.0087x; 2.0242x over previous
#include <cuda_runtime.h>
#include <cuda_bf16.h>
#include <mma.h>
#include <math.h>

using namespace nvcuda;

#define BB 128
#define TT 256
#define LL 512
#define HH 512
#define CC 95
#define ML 26

// ---------------- device scratch (static: no runtime allocation) ----------------
__device__ __align__(16) __nv_bfloat16 g_x16[BB * TT * LL];     // 32 MB
__device__ __align__(16) __nv_bfloat16 g_xEmb16[BB * TT * HH];  // 32 MB
__device__ __align__(16) __nv_bfloat16 g_Wi16[LL * HH];
__device__ __align__(16) __nv_bfloat16 g_Ws16[HH * HH];
__device__ __align__(16) __nv_bfloat16 g_Wih16[1536 * 1024];
__device__ __align__(16) __nv_bfloat16 g_Whh16[1536 * 512];
__device__ __align__(16) float g_WoutT[CC * HH];
__device__ __align__(16) float g_h[BB * HH];
__device__ __align__(16) __nv_bfloat16 g_h16[BB * HH];
__device__ __align__(16) __nv_bfloat16 g_inp16[BB * 1024];      // [emb(y) | ctx] bf16
__device__ __align__(16) float g_gates[BB * 3072];              // gi | gh (no bias)

// ---------------- FMA-only fast math (avoid MUFU pipe) --------------------------
__device__ __forceinline__ float fast_rcp_pos(float q) {
    float r = __uint_as_float(0x7EF127EAu - __float_as_uint(q));
    r = r * (2.0f - q * r);
    r = r * (2.0f - q * r);
    return r;
}

__device__ __forceinline__ float fast_tanh(float x) {
    float cx = fminf(fmaxf(x, -7.90531110763549805f), 7.90531110763549805f);
    float x2 = cx * cx;
    float p = fmaf(x2, -8.60467152213735e-11f, 5.12229709037114e-08f);
    p = fmaf(p, x2, 1.48572235717979e-05f);
    p = fmaf(p, x2, 6.37261928875436e-04f);
    p = fmaf(p, x2, 4.89352455891786e-03f);
    p = cx * p;
    float q = fmaf(x2, 1.19825839466702e-06f, 1.18534705686654e-04f);
    q = fmaf(q, x2, 2.26843463243900e-03f);
    q = fmaf(q, x2, 4.89352518554385e-03f);
    return p * fast_rcp_pos(q);
}

// ---------------- one-time helpers ----------------------------------------------
__global__ void init_kernel() {
    int i = blockIdx.x * 512 + threadIdx.x;
    g_h[i] = 0.f;
    g_h16[i] = __float2bfloat16(0.f);
}

__global__ void f2bf_kernel(const float* __restrict__ src,
                            __nv_bfloat16* __restrict__ dst) {
    int i = (blockIdx.x * 256 + threadIdx.x) * 4;
    float4 v = *(const float4*)(src + i);
    __nv_bfloat162* o = (__nv_bfloat162*)(dst + i);
    o[0] = __floats2bfloat162_rn(v.x, v.y);
    o[1] = __floats2bfloat162_rn(v.z, v.w);
}

__global__ void transpose_wout_kernel(const float* __restrict__ Wout) {
    int c = blockIdx.x;       // 0..94
    int k = threadIdx.x;      // 0..511
    g_WoutT[c * HH + k] = Wout[k * CC + c];
}

// ---------------- one-time: xEmb = x @ Wi + bi (bf16 tensor cores) --------------
// grid (8, 256), 256 threads. BM=128, BN=64, BK=32.
__global__ void xemb_wmma_kernel(const float* __restrict__ bias) {
    __shared__ __nv_bfloat16 As[128][32];
    __shared__ __nv_bfloat16 Bs[32][64];
    __shared__ float Co[128][64];
    const int tid = threadIdx.x;
    const int wid = tid >> 5;
    const int m0 = blockIdx.y * 128;
    const int n0 = blockIdx.x * 64;
    const int warpM = wid & 3;   // 4 groups of 32 rows
    const int warpN = wid >> 2;  // 2 groups of 32 cols

    wmma::fragment<wmma::accumulator, 16, 16, 16, float> c[2][2];
#pragma unroll
    for (int i = 0; i < 2; ++i)
#pragma unroll
        for (int j = 0; j < 2; ++j) wmma::fill_fragment(c[i][j], 0.f);

    for (int k0 = 0; k0 < 512; k0 += 32) {
#pragma unroll
        for (int i = 0; i < 2; ++i) {
            int idx = tid + i * 256;
            int m = idx >> 2, kq = idx & 3;
            *(uint4*)&As[m][kq * 8] =
                *(const uint4*)&g_x16[(size_t)(m0 + m) * 512 + k0 + kq * 8];
        }
        *(uint4*)&Bs[tid >> 3][(tid & 7) * 8] =
            *(const uint4*)&g_Wi16[(size_t)(k0 + (tid >> 3)) * 512 + n0 + (tid & 7) * 8];
        __syncthreads();
#pragma unroll
        for (int kk = 0; kk < 32; kk += 16) {
            wmma::fragment<wmma::matrix_a, 16, 16, 16, __nv_bfloat16, wmma::row_major> a[2];
            wmma::fragment<wmma::matrix_b, 16, 16, 16, __nv_bfloat16, wmma::row_major> b[2];
#pragma unroll
            for (int i = 0; i < 2; ++i)
                wmma::load_matrix_sync(a[i], &As[warpM * 32 + i * 16][kk], 32);
#pragma unroll
            for (int j = 0; j < 2; ++j)
                wmma::load_matrix_sync(b[j], &Bs[kk][warpN * 32 + j * 16], 64);
#pragma unroll
            for (int i = 0; i < 2; ++i)
#pragma unroll
                for (int j = 0; j < 2; ++j)
                    wmma::mma_sync(c[i][j], a[i], b[j], c[i][j]);
        }
        __syncthreads();
    }
#pragma unroll
    for (int i = 0; i < 2; ++i)
#pragma unroll
        for (int j = 0; j < 2; ++j)
            wmma::store_matrix_sync(&Co[warpM * 32 + i * 16][warpN * 32 + j * 16],
                                    c[i][j], 64, wmma::mem_row_major);
    __syncthreads();
#pragma unroll
    for (int it = 0; it < 32; ++it) {
        int idx = it * 256 + tid;
        int m = idx >> 6, cc = idx & 63;
        g_xEmb16[(size_t)(m0 + m) * 512 + n0 + cc] =
            __float2bfloat16(Co[m][cc] + bias[n0 + cc]);
    }
}

// ------ fused attention: sEmb + e + softmax + ctx + emb gather ------------------
// grid 128 (one block per b), 1024 threads
__global__ void attn_kernel(const float* __restrict__ wo,
                            const float* __restrict__ bo,
                            const float* __restrict__ bs,
                            const float* __restrict__ emb,
                            const int* __restrict__ targets, int step) {
    const int b = blockIdx.x;
    const int tid = threadIdx.x;
    __shared__ float hs[512], wos[512], sE[512], ew[256];
    __shared__ float red[16], redv[2];
    __shared__ float sPart[16 * 512];  // 32 KB; reused for ctx partials

    if (tid < 512) {
        hs[tid] = g_h[b * 512 + tid];
        wos[tid] = wo[tid];
    }
    __syncthreads();

    // ---- sEmb = h[b] @ Ws + bs (16-way k-split, 8 n per thread) ----
    {
        const int ks = tid >> 6;        // 0..15
        const int n0 = (tid & 63) * 8;  // 0..504
        float acc[8] = {};
#pragma unroll 4
        for (int kk = 0; kk < 32; ++kk) {
            int k = ks * 32 + kk;
            float hk = hs[k];
            union { uint4 u; __nv_bfloat162 h2[4]; } U;
            U.u = *(const uint4*)&g_Ws16[k * 512 + n0];
#pragma unroll
            for (int j = 0; j < 4; ++j) {
                float2 w = __bfloat1622float2(U.h2[j]);
                acc[2 * j] = fmaf(hk, w.x, acc[2 * j]);
                acc[2 * j + 1] = fmaf(hk, w.y, acc[2 * j + 1]);
            }
        }
#pragma unroll
        for (int j = 0; j < 8; ++j) sPart[ks * 512 + n0 + j] = acc[j];
    }
    __syncthreads();
    if (tid < 512) {
        float s = bs[tid];
#pragma unroll
        for (int i = 0; i < 16; ++i) s += sPart[i * 512 + tid];
        sE[tid] = s;
    }
    __syncthreads();

    // ---- e[t] = wo . tanh(xEmb[b,t,:] + sEmb) + bo  (4 threads per t) ----
    {
        const int t = tid >> 2, q = tid & 3;
        const __nv_bfloat16* row =
            g_xEmb16 + ((size_t)(b * 256 + t)) * 512 + q * 128;
        float acc = 0.f;
#pragma unroll
        for (int i = 0; i < 16; ++i) {
            union { uint4 u; __nv_bfloat162 h2[4]; } U;
            U.u = *(const uint4*)&row[i * 8];
            int base = q * 128 + i * 8;
#pragma unroll
            for (int j = 0; j < 4; ++j) {
                float2 v = __bfloat1622float2(U.h2[j]);
                int idx = base + 2 * j;
                acc = fmaf(wos[idx], fast_tanh(v.x + sE[idx]), acc);
                acc = fmaf(wos[idx + 1], fast_tanh(v.y + sE[idx + 1]), acc);
            }
        }
        acc += __shfl_xor_sync(0xffffffffu, acc, 1);
        acc += __shfl_xor_sync(0xffffffffu, acc, 2);
        if (q == 0) ew[t] = acc + bo[0];
    }
    __syncthreads();

    // ---- softmax over ew[256] ----
    if (tid < 256) {
        float v = ew[tid];
        float m = v;
#pragma unroll
        for (int off = 16; off > 0; off >>= 1)
            m = fmaxf(m, __shfl_xor_sync(0xffffffffu, m, off));
        if ((tid & 31) == 0) red[tid >> 5] = m;
    }
    __syncthreads();
    if (tid == 0) {
        float m = red[0];
#pragma unroll
        for (int w = 1; w < 8; ++w) m = fmaxf(m, red[w]);
        redv[0] = m;
    }
    __syncthreads();
    if (tid < 256) {
        float p = __expf(ew[tid] - redv[0]);
        ew[tid] = p;
        float s = p;
#pragma unroll
        for (int off = 16; off > 0; off >>= 1)
            s += __shfl_xor_sync(0xffffffffu, s, off);
        if ((tid & 31) == 0) red[8 + (tid >> 5)] = s;
    }
    __syncthreads();
    if (tid == 0) {
        float s = 0.f;
#pragma unroll
        for (int w = 0; w < 8; ++w) s += red[8 + w];
        redv[1] = 1.0f / s;
    }
    __syncthreads();
    if (tid < 256) ew[tid] *= redv[1];

    // emb gather -> g_inp16[:512]
    {
        int y = (step == 0) ? CC : targets[b * ML + step - 1];
        if (tid < 512)
            g_inp16[b * 1024 + tid] = __float2bfloat16(emb[y * 512 + tid]);
    }
    __syncthreads();

    // ---- ctx = aw @ x[b]  (4-way t-split, bf162 per thread) ----
    {
        const int d2 = tid & 255, tq = tid >> 8;  // tq 0..3
        const __nv_bfloat162* xb =
            (const __nv_bfloat162*)g_x16 + ((size_t)b * 256 + tq * 64) * 256 + d2;
        float ax = 0.f, ay = 0.f;
#pragma unroll 8
        for (int tt = 0; tt < 64; ++tt) {
            float a = ew[tq * 64 + tt];
            float2 v = __bfloat1622float2(xb[(size_t)tt * 256]);
            ax = fmaf(a, v.x, ax);
            ay = fmaf(a, v.y, ay);
        }
        sPart[tq * 512 + 2 * d2] = ax;
        sPart[tq * 512 + 2 * d2 + 1] = ay;
    }
    __syncthreads();
    if (tid < 512) {
        float c = sPart[tid] + sPart[512 + tid] + sPart[1024 + tid] + sPart[1536 + tid];
        g_inp16[b * 1024 + 512 + tid] = __float2bfloat16(c);
    }
}

// ---------- GRU gate GEMM (bf16 wmma): g_gates = [inp@W_ih^T | h@W_hh^T] --------
// grid 96 (48 gi + 48 gh), 256 threads. BM=128, BN=32, BK=32.
__global__ void gates_kernel() {
    __shared__ __nv_bfloat16 As[128][32];
    __shared__ __nv_bfloat16 Bs[32][32];
    const int tid = threadIdx.x;
    const int wid = tid >> 5;
    const bool hh = blockIdx.x >= 48;
    const __nv_bfloat16* A = hh ? g_h16 : g_inp16;
    const __nv_bfloat16* W = hh ? g_Whh16 : g_Wih16;
    const int K = hh ? 512 : 1024;
    const int n0 = (hh ? blockIdx.x - 48 : blockIdx.x) * 32;
    const int outc = (hh ? 1536 : 0) + n0;

    wmma::fragment<wmma::accumulator, 16, 16, 16, float> c[2];
    wmma::fill_fragment(c[0], 0.f);
    wmma::fill_fragment(c[1], 0.f);

    for (int k0 = 0; k0 < K; k0 += 32) {
#pragma unroll
        for (int i = 0; i < 2; ++i) {
            int idx = tid + i * 256;
            int m = idx >> 2, kq = idx & 3;
            *(uint4*)&As[m][kq * 8] =
                *(const uint4*)&A[(size_t)m * K + k0 + kq * 8];
        }
        if (tid < 128) {
            int j = tid >> 2, kq = tid & 3;
            *(uint4*)&Bs[j][kq * 8] =
                *(const uint4*)&W[(size_t)(n0 + j) * K + k0 + kq * 8];
        }
        __syncthreads();
#pragma unroll
        for (int kk = 0; kk < 32; kk += 16) {
            wmma::fragment<wmma::matrix_a, 16, 16, 16, __nv_bfloat16, wmma::row_major> a;
            wmma::load_matrix_sync(a, &As[wid * 16][kk], 32);
#pragma unroll
            for (int j = 0; j < 2; ++j) {
                wmma::fragment<wmma::matrix_b, 16, 16, 16, __nv_bfloat16, wmma::col_major> bfrag;
                wmma::load_matrix_sync(bfrag, &Bs[j * 16][kk], 32);
                wmma::mma_sync(c[j], a, bfrag, c[j]);
            }
        }
        __syncthreads();
    }
#pragma unroll
    for (int j = 0; j < 2; ++j)
        wmma::store_matrix_sync(&g_gates[(size_t)(wid * 16) * 3072 + outc + j * 16],
                                c[j], 3072, wmma::mem_row_major);
}

// ------ GRU pointwise (+biases) + output projection + log-softmax ---------------
__global__ void gru_out_kernel(const float* __restrict__ b_ih,
                               const float* __restrict__ b_hh,
                               const float* __restrict__ bout,
                               float* __restrict__ out, int step) {
    const int b = blockIdx.x;
    const int tid = threadIdx.x;  // 512
    const int lane = tid & 31, warp = tid >> 5;
    __shared__ float hs[HH];
    __shared__ float part[CC][4];
    __shared__ float lg[CC];
    __shared__ float red[8];
    __shared__ float red2[2];
    const float* g = g_gates + b * 3072;
    float gir = g[tid] + b_ih[tid];
    float giz = g[tid + 512] + b_ih[tid + 512];
    float gin = g[tid + 1024] + b_ih[tid + 1024];
    float ghr = g[tid + 1536] + b_hh[tid];
    float ghz = g[tid + 2048] + b_hh[tid + 512];
    float ghn = g[tid + 2560] + b_hh[tid + 1024];
    float r = 1.f / (1.f + __expf(-(gir + ghr)));
    float z = 1.f / (1.f + __expf(-(giz + ghz)));
    float n = fast_tanh(gin + r * ghn);
    float hv = (1.f - z) * n + z * g_h[b * HH + tid];
    g_h[b * HH + tid] = hv;
    g_h16[b * HH + tid] = __float2bfloat16(hv);
    hs[tid] = hv;
    __syncthreads();
    if (tid < 380) {
        int c = tid >> 2, ks = tid & 3;
        const float4* wp = (const float4*)(g_WoutT + c * HH + ks * 128);
        const float4* hp = (const float4*)(hs + ks * 128);
        float acc = 0.f;
#pragma unroll 8
        for (int k = 0; k < 32; ++k) {
            float4 h4 = hp[k], w4 = wp[k];
            acc = fmaf(h4.x, w4.x, acc);
            acc = fmaf(h4.y, w4.y, acc);
            acc = fmaf(h4.z, w4.z, acc);
            acc = fmaf(h4.w, w4.w, acc);
        }
        part[c][ks] = acc;
    }
    __syncthreads();
    if (tid < CC)
        lg[tid] = part[tid][0] + part[tid][1] + part[tid][2] + part[tid][3] +
                  bout[tid];
    __syncthreads();
    if (tid < 128) {
        float v = (tid < CC) ? lg[tid] : -1e30f;
        float m = v;
#pragma unroll
        for (int off = 16; off > 0; off >>= 1)
            m = fmaxf(m, __shfl_xor_sync(0xffffffffu, m, off));
        if (lane == 0) red[warp] = m;
    }
    __syncthreads();
    if (tid == 0)
        red2[0] = fmaxf(fmaxf(red[0], red[1]), fmaxf(red[2], red[3]));
    __syncthreads();
    if (tid < 128) {
        float v = (tid < CC) ? __expf(lg[tid] - red2[0]) : 0.f;
#pragma unroll
        for (int off = 16; off > 0; off >>= 1)
            v += __shfl_xor_sync(0xffffffffu, v, off);
        if (lane == 0) red[4 + warp] = v;
    }
    __syncthreads();
    if (tid == 0)
        red2[1] = logf(red[4] + red[5] + red[6] + red[7]);
    __syncthreads();
    if (tid < CC)
        out[(size_t)step * BB * CC + b * CC + tid] =
            lg[tid] - red2[0] - red2[1];
}

__global__ void convert_x_kernel(const float* __restrict__ x) {
    int i = (blockIdx.x * 256 + threadIdx.x) * 4;
    float4 v = *(const float4*)(x + i);
    __nv_bfloat162* o = (__nv_bfloat162*)(g_x16 + i);
    o[0] = __floats2bfloat162_rn(v.x, v.y);
    o[1] = __floats2bfloat162_rn(v.z, v.w);
}

// --------------------------------- launcher -------------------------------------
extern "C" void kernel_launch(void* const* d_in, const int* in_sizes, int n_in,
                              void* d_out, int out_size) {
    (void)in_sizes; (void)n_in; (void)out_size;
    const float* x       = (const float*)d_in[0];
    const int*   targets = (const int*)  d_in[1];
    const float* emb     = (const float*)d_in[2];
    const float* Wi      = (const float*)d_in[3];
    const float* bi      = (const float*)d_in[4];
    const float* Ws      = (const float*)d_in[5];
    const float* bs      = (const float*)d_in[6];
    const float* wo      = (const float*)d_in[7];
    const float* bo      = (const float*)d_in[8];
    const float* W_ih    = (const float*)d_in[9];
    const float* W_hh    = (const float*)d_in[10];
    const float* b_ih    = (const float*)d_in[11];
    const float* b_hh    = (const float*)d_in[12];
    const float* Wout    = (const float*)d_in[13];
    const float* bout    = (const float*)d_in[14];
    float* out = (float*)d_out;

    __nv_bfloat16 *p_Wi16, *p_Ws16, *p_Wih16, *p_Whh16;
    cudaGetSymbolAddress((void**)&p_Wi16, g_Wi16);
    cudaGetSymbolAddress((void**)&p_Ws16, g_Ws16);
    cudaGetSymbolAddress((void**)&p_Wih16, g_Wih16);
    cudaGetSymbolAddress((void**)&p_Whh16, g_Whh16);

    // one-time
    init_kernel<<<128, 512>>>();
    convert_x_kernel<<<(BB * TT * LL) / 1024, 256>>>(x);
    f2bf_kernel<<<(LL * HH) / 1024, 256>>>(Wi, p_Wi16);
    f2bf_kernel<<<(HH * HH) / 1024, 256>>>(Ws, p_Ws16);
    f2bf_kernel<<<(1536 * 1024) / 1024, 256>>>(W_ih, p_Wih16);
    f2bf_kernel<<<(1536 * 512) / 1024, 256>>>(W_hh, p_Whh16);
    transpose_wout_kernel<<<CC, 512>>>(Wout);
    xemb_wmma_kernel<<<dim3(8, 256), 256>>>(bi);

    for (int step = 0; step < ML; ++step) {
        attn_kernel<<<BB, 1024>>>(wo, bo, bs, emb, targets, step);
        gates_kernel<<<96, 256>>>();
        gru_out_kernel<<<BB, 512>>>(b_ih, b_hh, bout, out, step);
    }
}

// round 5
// speedup vs baseline: 4.5822x; 1.1431x over previous
#include <cuda_runtime.h>
#include <cuda_bf16.h>
#include <mma.h>
#include <math.h>

using namespace nvcuda;

#define BB 128
#define TT 256
#define LL 512
#define HH 512
#define CC 95
#define ML 26

// ---------------- device scratch (static: no runtime allocation) ----------------
__device__ __align__(16) __nv_bfloat16 g_x16[BB * TT * LL];     // 32 MB
__device__ __align__(16) __nv_bfloat16 g_xEmb16[BB * TT * HH];  // 32 MB
__device__ __align__(16) __nv_bfloat16 g_Wi16[LL * HH];
__device__ __align__(16) __nv_bfloat16 g_Ws16[HH * HH];
__device__ __align__(16) __nv_bfloat16 g_Wih16[1536 * 1024];
__device__ __align__(16) __nv_bfloat16 g_Whh16[1536 * 512];
__device__ __align__(16) __nv_bfloat16 g_embSeq[ML * BB * HH];  // teacher-forced emb rows
__device__ __align__(16) float g_giEmb[ML * BB * 1536];         // 20 MB, precomputed gi emb part
__device__ __align__(16) float g_WoutT[CC * HH];
__device__ __align__(16) float g_h[BB * HH];
__device__ __align__(16) __nv_bfloat16 g_h16[BB * HH];
__device__ __align__(16) __nv_bfloat16 g_ctx16[BB * HH];
__device__ __align__(16) float g_gates[BB * 3072];              // gi | gh (no bias)

// ---------------- fast math --------------------------------------------------
__device__ __forceinline__ float tanh_mufu(float x) {
    float y;
    asm("tanh.approx.f32 %0, %1;" : "=f"(y) : "f"(x));
    return y;
}

__device__ __forceinline__ float fast_rcp_pos(float q) {
    float r = __uint_as_float(0x7EF127EAu - __float_as_uint(q));
    r = r * (2.0f - q * r);
    r = r * (2.0f - q * r);
    return r;
}

__device__ __forceinline__ float fast_tanh(float x) {  // accurate FMA-only (GRU n)
    float cx = fminf(fmaxf(x, -7.90531110763549805f), 7.90531110763549805f);
    float x2 = cx * cx;
    float p = fmaf(x2, -8.60467152213735e-11f, 5.12229709037114e-08f);
    p = fmaf(p, x2, 1.48572235717979e-05f);
    p = fmaf(p, x2, 6.37261928875436e-04f);
    p = fmaf(p, x2, 4.89352455891786e-03f);
    p = cx * p;
    float q = fmaf(x2, 1.19825839466702e-06f, 1.18534705686654e-04f);
    q = fmaf(q, x2, 2.26843463243900e-03f);
    q = fmaf(q, x2, 4.89352518554385e-03f);
    return p * fast_rcp_pos(q);
}

// ---------------- one-time helpers ----------------------------------------------
__global__ void init_kernel() {
    int i = blockIdx.x * 512 + threadIdx.x;
    g_h[i] = 0.f;
    g_h16[i] = __float2bfloat16(0.f);
}

__global__ void f2bf_kernel(const float* __restrict__ src,
                            __nv_bfloat16* __restrict__ dst) {
    int i = (blockIdx.x * 256 + threadIdx.x) * 4;
    float4 v = *(const float4*)(src + i);
    __nv_bfloat162* o = (__nv_bfloat162*)(dst + i);
    o[0] = __floats2bfloat162_rn(v.x, v.y);
    o[1] = __floats2bfloat162_rn(v.z, v.w);
}

__global__ void convert_x_kernel(const float* __restrict__ x) {
    int i = (blockIdx.x * 256 + threadIdx.x) * 4;
    float4 v = *(const float4*)(x + i);
    __nv_bfloat162* o = (__nv_bfloat162*)(g_x16 + i);
    o[0] = __floats2bfloat162_rn(v.x, v.y);
    o[1] = __floats2bfloat162_rn(v.z, v.w);
}

__global__ void transpose_wout_kernel(const float* __restrict__ Wout) {
    int c = blockIdx.x;
    int k = threadIdx.x;
    g_WoutT[c * HH + k] = Wout[k * CC + c];
}

// gather emb rows for all teacher-forced tokens: [26*128][512] bf16
__global__ void embseq_kernel(const float* __restrict__ emb,
                              const int* __restrict__ targets) {
    int m = blockIdx.x;            // 0..3327
    int step = m >> 7, b = m & 127;
    int y = (step == 0) ? CC : targets[b * ML + step - 1];
    int k = threadIdx.x * 4;       // 128 threads * 4
    float4 v = *(const float4*)(emb + y * HH + k);
    __nv_bfloat162* o = (__nv_bfloat162*)(g_embSeq + (size_t)m * HH + k);
    o[0] = __floats2bfloat162_rn(v.x, v.y);
    o[1] = __floats2bfloat162_rn(v.z, v.w);
}

// ---------------- one-time: xEmb = x @ Wi + bi (bf16 wmma, 128x128 tiles) -------
__global__ void xemb_wmma_kernel(const float* __restrict__ bias) {
    extern __shared__ char dyn[];
    __nv_bfloat16 (*As)[32] = (__nv_bfloat16(*)[32])dyn;              // 128x32
    __nv_bfloat16 (*Bs)[128] = (__nv_bfloat16(*)[128])(dyn + 8192);   // 32x128
    float (*Co)[128] = (float(*)[128])(dyn + 16384);                  // 128x128
    const int tid = threadIdx.x;
    const int wid = tid >> 5;
    const int m0 = blockIdx.y * 128;
    const int n0 = blockIdx.x * 128;
    const int warpM = wid & 3;
    const int warpN = wid >> 2;

    wmma::fragment<wmma::accumulator, 16, 16, 16, float> c[2][4];
#pragma unroll
    for (int i = 0; i < 2; ++i)
#pragma unroll
        for (int j = 0; j < 4; ++j) wmma::fill_fragment(c[i][j], 0.f);

    for (int k0 = 0; k0 < 512; k0 += 32) {
#pragma unroll
        for (int i = 0; i < 2; ++i) {
            int idx = tid + i * 256;
            int m = idx >> 2, kq = idx & 3;
            *(uint4*)&As[m][kq * 8] =
                *(const uint4*)&g_x16[(size_t)(m0 + m) * 512 + k0 + kq * 8];
        }
#pragma unroll
        for (int i = 0; i < 2; ++i) {
            int idx = tid + i * 256;
            int k = idx >> 4, q = idx & 15;
            *(uint4*)&Bs[k][q * 8] =
                *(const uint4*)&g_Wi16[(size_t)(k0 + k) * 512 + n0 + q * 8];
        }
        __syncthreads();
#pragma unroll
        for (int kk = 0; kk < 32; kk += 16) {
            wmma::fragment<wmma::matrix_a, 16, 16, 16, __nv_bfloat16, wmma::row_major> a[2];
            wmma::fragment<wmma::matrix_b, 16, 16, 16, __nv_bfloat16, wmma::row_major> b[4];
#pragma unroll
            for (int i = 0; i < 2; ++i)
                wmma::load_matrix_sync(a[i], &As[warpM * 32 + i * 16][kk], 32);
#pragma unroll
            for (int j = 0; j < 4; ++j)
                wmma::load_matrix_sync(b[j], &Bs[kk][warpN * 64 + j * 16], 128);
#pragma unroll
            for (int i = 0; i < 2; ++i)
#pragma unroll
                for (int j = 0; j < 4; ++j)
                    wmma::mma_sync(c[i][j], a[i], b[j], c[i][j]);
        }
        __syncthreads();
    }
#pragma unroll
    for (int i = 0; i < 2; ++i)
#pragma unroll
        for (int j = 0; j < 4; ++j)
            wmma::store_matrix_sync(&Co[warpM * 32 + i * 16][warpN * 64 + j * 16],
                                    c[i][j], 128, wmma::mem_row_major);
    __syncthreads();
#pragma unroll
    for (int it = 0; it < 64; ++it) {
        int idx = it * 256 + tid;
        int m = idx >> 7, cc = idx & 127;
        g_xEmb16[(size_t)(m0 + m) * 512 + n0 + cc] =
            __float2bfloat16(Co[m][cc] + bias[n0 + cc]);
    }
}

// ------ one-time: giEmb = embSeq @ W_ih[:, :512]^T  [3328,1536] fp32 ------------
__global__ void giemb_wmma_kernel() {
    __shared__ __nv_bfloat16 As[128][32];
    __shared__ __nv_bfloat16 Bs[64][32];
    const int tid = threadIdx.x;
    const int wid = tid >> 5;
    const int m0 = blockIdx.y * 128;
    const int n0 = blockIdx.x * 64;

    wmma::fragment<wmma::accumulator, 16, 16, 16, float> c[4];
#pragma unroll
    for (int j = 0; j < 4; ++j) wmma::fill_fragment(c[j], 0.f);

    for (int k0 = 0; k0 < 512; k0 += 32) {
#pragma unroll
        for (int i = 0; i < 2; ++i) {
            int idx = tid + i * 256;
            int m = idx >> 2, kq = idx & 3;
            *(uint4*)&As[m][kq * 8] =
                *(const uint4*)&g_embSeq[(size_t)(m0 + m) * 512 + k0 + kq * 8];
        }
        {
            int j = tid >> 2, kq = tid & 3;  // 256 -> 64 rows x 4 quads
            *(uint4*)&Bs[j][kq * 8] =
                *(const uint4*)&g_Wih16[(size_t)(n0 + j) * 1024 + k0 + kq * 8];
        }
        __syncthreads();
#pragma unroll
        for (int kk = 0; kk < 32; kk += 16) {
            wmma::fragment<wmma::matrix_a, 16, 16, 16, __nv_bfloat16, wmma::row_major> a;
            wmma::load_matrix_sync(a, &As[wid * 16][kk], 32);
#pragma unroll
            for (int j = 0; j < 4; ++j) {
                wmma::fragment<wmma::matrix_b, 16, 16, 16, __nv_bfloat16, wmma::col_major> bf;
                wmma::load_matrix_sync(bf, &Bs[j * 16][kk], 32);
                wmma::mma_sync(c[j], a, bf, c[j]);
            }
        }
        __syncthreads();
    }
#pragma unroll
    for (int j = 0; j < 4; ++j)
        wmma::store_matrix_sync(&g_giEmb[(size_t)(m0 + wid * 16) * 1536 + n0 + j * 16],
                                c[j], 1536, wmma::mem_row_major);
}

// ---------------- shared attention body (escore + softmax + ctx) ----------------
__device__ __forceinline__ void attn_body(int b, int tid,
                                          float* sE, float* wos, float* ew,
                                          float* red, float* redv, float* sPart,
                                          const float* bo) {
    // e[t] = wo . tanh(xEmb[b,t,:] + sE) + bo   (4 threads per t, MUFU tanh)
    {
        const int t = tid >> 2, q = tid & 3;
        const __nv_bfloat16* row =
            g_xEmb16 + ((size_t)(b * 256 + t)) * 512 + q * 128;
        float acc = 0.f;
#pragma unroll
        for (int i = 0; i < 16; ++i) {
            union { uint4 u; __nv_bfloat162 h2[4]; } U;
            U.u = *(const uint4*)&row[i * 8];
            int base = q * 128 + i * 8;
#pragma unroll
            for (int j = 0; j < 4; ++j) {
                float2 v = __bfloat1622float2(U.h2[j]);
                int idx = base + 2 * j;
                acc = fmaf(wos[idx], tanh_mufu(v.x + sE[idx]), acc);
                acc = fmaf(wos[idx + 1], tanh_mufu(v.y + sE[idx + 1]), acc);
            }
        }
        acc += __shfl_xor_sync(0xffffffffu, acc, 1);
        acc += __shfl_xor_sync(0xffffffffu, acc, 2);
        if (q == 0) ew[t] = acc + bo[0];
    }
    __syncthreads();

    // softmax over ew[256]
    if (tid < 256) {
        float v = ew[tid];
        float m = v;
#pragma unroll
        for (int off = 16; off > 0; off >>= 1)
            m = fmaxf(m, __shfl_xor_sync(0xffffffffu, m, off));
        if ((tid & 31) == 0) red[tid >> 5] = m;
    }
    __syncthreads();
    if (tid == 0) {
        float m = red[0];
#pragma unroll
        for (int w = 1; w < 8; ++w) m = fmaxf(m, red[w]);
        redv[0] = m;
    }
    __syncthreads();
    if (tid < 256) {
        float p = __expf(ew[tid] - redv[0]);
        ew[tid] = p;
        float s = p;
#pragma unroll
        for (int off = 16; off > 0; off >>= 1)
            s += __shfl_xor_sync(0xffffffffu, s, off);
        if ((tid & 31) == 0) red[8 + (tid >> 5)] = s;
    }
    __syncthreads();
    if (tid == 0) {
        float s = 0.f;
#pragma unroll
        for (int w = 0; w < 8; ++w) s += red[8 + w];
        redv[1] = 1.0f / s;
    }
    __syncthreads();
    if (tid < 256) ew[tid] *= redv[1];
    __syncthreads();

    // ctx = aw @ x[b] (4-way t-split)
    {
        const int d2 = tid & 255, tq = tid >> 8;
        const __nv_bfloat162* xb =
            (const __nv_bfloat162*)g_x16 + ((size_t)b * 256 + tq * 64) * 256 + d2;
        float ax = 0.f, ay = 0.f;
#pragma unroll 8
        for (int tt = 0; tt < 64; ++tt) {
            float a = ew[tq * 64 + tt];
            float2 v = __bfloat1622float2(xb[(size_t)tt * 256]);
            ax = fmaf(a, v.x, ax);
            ay = fmaf(a, v.y, ay);
        }
        sPart[tq * 512 + 2 * d2] = ax;
        sPart[tq * 512 + 2 * d2 + 1] = ay;
    }
    __syncthreads();
    if (tid < 512) {
        float c = sPart[tid] + sPart[512 + tid] + sPart[1024 + tid] + sPart[1536 + tid];
        g_ctx16[b * 512 + tid] = __float2bfloat16(c);
    }
}

// ---------------- step 0 attention (h = 0 -> sEmb = bs) -------------------------
__global__ void attn0_kernel(const float* __restrict__ wo,
                             const float* __restrict__ bo,
                             const float* __restrict__ bs) {
    const int b = blockIdx.x;
    const int tid = threadIdx.x;
    __shared__ float sE[512], wos[512], ew[256], red[16], redv[2];
    __shared__ float sPart[4 * 512];
    if (tid < 512) {
        sE[tid] = bs[tid];
        wos[tid] = wo[tid];
    }
    __syncthreads();
    attn_body(b, tid, sE, wos, ew, red, redv, sPart, bo);
}

// ---------- per-step gates GEMM: g_gates = [ctx@Wc^T + giEmb | h@Whh^T] ---------
// grid 96 (48 gi + 48 gh), 256 threads, K=512 both halves
__global__ void gates_kernel(int step) {
    __shared__ __nv_bfloat16 As[128][32];
    __shared__ __nv_bfloat16 Bs[32][32];
    const int tid = threadIdx.x;
    const int wid = tid >> 5;
    const bool hh = blockIdx.x >= 48;
    const __nv_bfloat16* A = hh ? g_h16 : g_ctx16;
    const __nv_bfloat16* W = hh ? g_Whh16 : g_Wih16;
    const int ldw = hh ? 512 : 1024;
    const int koff = hh ? 0 : 512;
    const int n0 = (hh ? blockIdx.x - 48 : blockIdx.x) * 32;
    const int outc = (hh ? 1536 : 0) + n0;

    wmma::fragment<wmma::accumulator, 16, 16, 16, float> c[2];
    if (hh) {
        wmma::fill_fragment(c[0], 0.f);
        wmma::fill_fragment(c[1], 0.f);
    } else {
        const float* gi = g_giEmb + ((size_t)step * 128 + wid * 16) * 1536 + n0;
        wmma::load_matrix_sync(c[0], gi, 1536, wmma::mem_row_major);
        wmma::load_matrix_sync(c[1], gi + 16, 1536, wmma::mem_row_major);
    }

    for (int k0 = 0; k0 < 512; k0 += 32) {
#pragma unroll
        for (int i = 0; i < 2; ++i) {
            int idx = tid + i * 256;
            int m = idx >> 2, kq = idx & 3;
            *(uint4*)&As[m][kq * 8] =
                *(const uint4*)&A[(size_t)m * 512 + k0 + kq * 8];
        }
        if (tid < 128) {
            int j = tid >> 2, kq = tid & 3;
            *(uint4*)&Bs[j][kq * 8] =
                *(const uint4*)&W[(size_t)(n0 + j) * ldw + koff + k0 + kq * 8];
        }
        __syncthreads();
#pragma unroll
        for (int kk = 0; kk < 32; kk += 16) {
            wmma::fragment<wmma::matrix_a, 16, 16, 16, __nv_bfloat16, wmma::row_major> a;
            wmma::load_matrix_sync(a, &As[wid * 16][kk], 32);
#pragma unroll
            for (int j = 0; j < 2; ++j) {
                wmma::fragment<wmma::matrix_b, 16, 16, 16, __nv_bfloat16, wmma::col_major> bf;
                wmma::load_matrix_sync(bf, &Bs[j * 16][kk], 32);
                wmma::mma_sync(c[j], a, bf, c[j]);
            }
        }
        __syncthreads();
    }
#pragma unroll
    for (int j = 0; j < 2; ++j)
        wmma::store_matrix_sync(&g_gates[(size_t)(wid * 16) * 3072 + outc + j * 16],
                                c[j], 3072, wmma::mem_row_major);
}

// ------ fused: GRU pointwise + logits + log-softmax + sEmb + attention ----------
// grid 128, 1024 threads
__global__ void fused_kernel(const float* __restrict__ b_ih,
                             const float* __restrict__ b_hh,
                             const float* __restrict__ bout,
                             const float* __restrict__ wo,
                             const float* __restrict__ bo,
                             const float* __restrict__ bs,
                             float* __restrict__ out, int step) {
    const int b = blockIdx.x;
    const int tid = threadIdx.x;
    const int lane = tid & 31, warp = tid >> 5;
    __shared__ float hs[512], sE[512], wos[512], ew[256];
    __shared__ float part[CC][4], lg[CC], red[16], redv[2], red2[2];
    __shared__ float sPart[16 * 512];

    // ---- GRU pointwise update ----
    if (tid < 512) {
        const float* g = g_gates + b * 3072;
        float gir = g[tid] + b_ih[tid];
        float giz = g[tid + 512] + b_ih[tid + 512];
        float gin = g[tid + 1024] + b_ih[tid + 1024];
        float ghr = g[tid + 1536] + b_hh[tid];
        float ghz = g[tid + 2048] + b_hh[tid + 512];
        float ghn = g[tid + 2560] + b_hh[tid + 1024];
        float r = 1.f / (1.f + __expf(-(gir + ghr)));
        float z = 1.f / (1.f + __expf(-(giz + ghz)));
        float n = fast_tanh(gin + r * ghn);
        float hv = (1.f - z) * n + z * g_h[b * 512 + tid];
        g_h[b * 512 + tid] = hv;
        g_h16[b * 512 + tid] = __float2bfloat16(hv);
        hs[tid] = hv;
        wos[tid] = wo[tid];
    }
    __syncthreads();

    // ---- logits + log-softmax ----
    if (tid < 380) {
        int c = tid >> 2, ks = tid & 3;
        const float4* wp = (const float4*)(g_WoutT + c * 512 + ks * 128);
        const float4* hp = (const float4*)(hs + ks * 128);
        float acc = 0.f;
#pragma unroll 8
        for (int k = 0; k < 32; ++k) {
            float4 h4 = hp[k], w4 = wp[k];
            acc = fmaf(h4.x, w4.x, acc);
            acc = fmaf(h4.y, w4.y, acc);
            acc = fmaf(h4.z, w4.z, acc);
            acc = fmaf(h4.w, w4.w, acc);
        }
        part[c][ks] = acc;
    }
    __syncthreads();
    if (tid < CC)
        lg[tid] = part[tid][0] + part[tid][1] + part[tid][2] + part[tid][3] +
                  bout[tid];
    __syncthreads();
    if (tid < 128) {
        float v = (tid < CC) ? lg[tid] : -1e30f;
        float m = v;
#pragma unroll
        for (int off = 16; off > 0; off >>= 1)
            m = fmaxf(m, __shfl_xor_sync(0xffffffffu, m, off));
        if (lane == 0) red[12 + warp] = m;
    }
    __syncthreads();
    if (tid == 0)
        red2[0] = fmaxf(fmaxf(red[12], red[13]), fmaxf(red[14], red[15]));
    __syncthreads();
    if (tid < 128) {
        float v = (tid < CC) ? __expf(lg[tid] - red2[0]) : 0.f;
#pragma unroll
        for (int off = 16; off > 0; off >>= 1)
            v += __shfl_xor_sync(0xffffffffu, v, off);
        if (lane == 0) red[12 + warp] = v;
    }
    __syncthreads();
    if (tid == 0)
        red2[1] = logf(red[12] + red[13] + red[14] + red[15]);
    __syncthreads();
    if (tid < CC)
        out[(size_t)step * BB * CC + b * CC + tid] =
            lg[tid] - red2[0] - red2[1];

    if (step == ML - 1) return;  // last step: no next attention

    // ---- sEmb = h @ Ws + bs (16-way k-split) ----
    {
        const int ks = tid >> 6;
        const int n0 = (tid & 63) * 8;
        float acc[8] = {};
#pragma unroll 4
        for (int kk = 0; kk < 32; ++kk) {
            int k = ks * 32 + kk;
            float hk = hs[k];
            union { uint4 u; __nv_bfloat162 h2[4]; } U;
            U.u = *(const uint4*)&g_Ws16[k * 512 + n0];
#pragma unroll
            for (int j = 0; j < 4; ++j) {
                float2 w = __bfloat1622float2(U.h2[j]);
                acc[2 * j] = fmaf(hk, w.x, acc[2 * j]);
                acc[2 * j + 1] = fmaf(hk, w.y, acc[2 * j + 1]);
            }
        }
#pragma unroll
        for (int j = 0; j < 8; ++j) sPart[ks * 512 + n0 + j] = acc[j];
    }
    __syncthreads();
    if (tid < 512) {
        float s = bs[tid];
#pragma unroll
        for (int i = 0; i < 16; ++i) s += sPart[i * 512 + tid];
        sE[tid] = s;
    }
    __syncthreads();

    attn_body(b, tid, sE, wos, ew, red, redv, sPart, bo);
}

// --------------------------------- launcher -------------------------------------
extern "C" void kernel_launch(void* const* d_in, const int* in_sizes, int n_in,
                              void* d_out, int out_size) {
    (void)in_sizes; (void)n_in; (void)out_size;
    const float* x       = (const float*)d_in[0];
    const int*   targets = (const int*)  d_in[1];
    const float* emb     = (const float*)d_in[2];
    const float* Wi      = (const float*)d_in[3];
    const float* bi      = (const float*)d_in[4];
    const float* Ws      = (const float*)d_in[5];
    const float* bs      = (const float*)d_in[6];
    const float* wo      = (const float*)d_in[7];
    const float* bo      = (const float*)d_in[8];
    const float* W_ih    = (const float*)d_in[9];
    const float* W_hh    = (const float*)d_in[10];
    const float* b_ih    = (const float*)d_in[11];
    const float* b_hh    = (const float*)d_in[12];
    const float* Wout    = (const float*)d_in[13];
    const float* bout    = (const float*)d_in[14];
    float* out = (float*)d_out;

    __nv_bfloat16 *p_Wi16, *p_Ws16, *p_Wih16, *p_Whh16;
    cudaGetSymbolAddress((void**)&p_Wi16, g_Wi16);
    cudaGetSymbolAddress((void**)&p_Ws16, g_Ws16);
    cudaGetSymbolAddress((void**)&p_Wih16, g_Wih16);
    cudaGetSymbolAddress((void**)&p_Whh16, g_Whh16);

    static bool attr_set = false;
    if (!attr_set) {
        cudaFuncSetAttribute(xemb_wmma_kernel,
                             cudaFuncAttributeMaxDynamicSharedMemorySize, 81920);
        attr_set = true;
    }

    // one-time preprocessing
    init_kernel<<<128, 512>>>();
    convert_x_kernel<<<(BB * TT * LL) / 1024, 256>>>(x);
    f2bf_kernel<<<(LL * HH) / 1024, 256>>>(Wi, p_Wi16);
    f2bf_kernel<<<(HH * HH) / 1024, 256>>>(Ws, p_Ws16);
    f2bf_kernel<<<(1536 * 1024) / 1024, 256>>>(W_ih, p_Wih16);
    f2bf_kernel<<<(1536 * 512) / 1024, 256>>>(W_hh, p_Whh16);
    transpose_wout_kernel<<<CC, 512>>>(Wout);
    embseq_kernel<<<ML * BB, 128>>>(emb, targets);
    xemb_wmma_kernel<<<dim3(4, 256), 256, 81920>>>(bi);
    giemb_wmma_kernel<<<dim3(1536 / 64, ML * BB / 128), 256>>>();

    // step 0 attention (h = 0)
    attn0_kernel<<<BB, 1024>>>(wo, bo, bs);

    for (int step = 0; step < ML; ++step) {
        gates_kernel<<<96, 256>>>(step);
        fused_kernel<<<BB, 1024>>>(b_ih, b_hh, bout, wo, bo, bs, out, step);
    }
}